// round 15
// baseline (speedup 1.0000x reference)
#include <cuda_runtime.h>

#define HIDDEN  20
#define N_MID   8

#define CB     0.5f
#define CC     0.5f
#define CSIGMA 1.0f
#define CBF    0.5f
#define CCF    0.9f

typedef unsigned long long ull;

// ---------------- packed f32x2 helpers (Blackwell) ----------------
__device__ __forceinline__ ull pack2(float lo, float hi) {
    ull r;
    asm("mov.b64 %0, {%1, %2};" : "=l"(r) : "f"(lo), "f"(hi));
    return r;
}
__device__ __forceinline__ void unpack2(ull p, float& lo, float& hi) {
    asm("mov.b64 {%0, %1}, %2;" : "=f"(lo), "=f"(hi) : "l"(p));
}
__device__ __forceinline__ ull fma2(ull a, ull b, ull c) {
    ull r;
    asm("fma.rn.f32x2 %0, %1, %2, %3;" : "=l"(r) : "l"(a), "l"(b), "l"(c));
    return r;
}

// Hardware tanh: single MUFU.TANH (abs err ~2^-11; final rel_err ~2e-5, safe).
__device__ __forceinline__ float tanh_fast(float z) {
    float r;
    asm("tanh.approx.f32 %0, %1;" : "=f"(r) : "f"(z));
    return r;
}

// One mid layer: (hu,vw) -> (nhu,nvw). Single accumulator pair per stream
// (bank-bound regime: 2 chains x rt3 = 6 cyc/step > lat 5 -> no ILP loss).
__device__ __forceinline__ void mid_layer(const ull* __restrict__ Wl,
                                          const ull* __restrict__ bl,
                                          const ull hu[HIDDEN],
                                          const ull vw[HIDDEN],
                                          ull nhu[HIDDEN],
                                          ull nvw[HIDDEN])
{
    #pragma unroll
    for (int j = 0; j < HIDDEN; j++) {
        ull zhu = bl[j];                  // (b, 0)
        ull zvw = 0ull;
        const ulonglong2* __restrict__ Wrow =
            reinterpret_cast<const ulonglong2*>(&Wl[j * HIDDEN]);
        #pragma unroll
        for (int k2 = 0; k2 < HIDDEN / 2; k2++) {
            const ulonglong2 ww = Wrow[k2];          // LDS.128: (w_k,w_k),(w_k1,w_k1)
            const int k = 2 * k2;
            zhu = fma2(ww.x, hu[k],     zhu);
            zvw = fma2(ww.x, vw[k],     zvw);
            zhu = fma2(ww.y, hu[k + 1], zhu);
            zvw = fma2(ww.y, vw[k + 1], zvw);
        }
        float z, zu, zv, zw;
        unpack2(zhu, z, zu);
        unpack2(zvw, zv, zw);
        const float a  = tanh_fast(z);
        const float d  = fmaf(-a, a, 1.0f);
        const float nv = d * zv;
        const float t  = (-2.0f) * (a * nv);   // FMUL-imm (rt=1) + FMUL
        nhu[j] = pack2(a, d * zu);
        nvw[j] = pack2(nv, fmaf(t, zv, d * zw));
    }
}

#define BLOCK 64   // 4 CTAs/SM (regs 238*64*4 = 60.9K <= 64K RF): finer-grain
                   // wave overlap, fill of incoming CTA hidden behind 3 others

__global__ __launch_bounds__(BLOCK, 1)
void pde_mlp_kernel(const float* __restrict__ x,
                    const float* __restrict__ W_in,
                    const float* __restrict__ b_in,
                    const float* __restrict__ W_mid,
                    const float* __restrict__ b_mid,
                    const float* __restrict__ W_out,
                    const float* __restrict__ b_out,
                    float* __restrict__ out,
                    int n)
{
    __shared__ __align__(16) ull sW2[N_MID * HIDDEN * HIDDEN];   // (w,w) pairs, 25.6 KB
    __shared__ ull sB2[N_MID * HIDDEN];                          // (b,0)
    __shared__ __align__(16) ull sWout2[HIDDEN];
    __shared__ float sWin[HIDDEN * 2];
    __shared__ float sbin[HIDDEN];
    __shared__ float sbout;

    const int tid = threadIdx.x;
    const int gid = blockIdx.x * BLOCK + tid;

    // Hoisted point load: LDG issues before the fill, latency hidden behind it.
    float2 xi = make_float2(0.0f, 0.0f);
    if (gid < n) xi = reinterpret_cast<const float2*>(x)[gid];

    // ---- weight fill, vectorized: float4 LDG.128 ----
    {
        const float4* __restrict__ Wm4 = reinterpret_cast<const float4*>(W_mid);
        #pragma unroll 1
        for (int i = tid; i < (N_MID * HIDDEN * HIDDEN) / 4; i += BLOCK) {
            const float4 wv = Wm4[i];
            sW2[4 * i + 0] = pack2(wv.x, wv.x);
            sW2[4 * i + 1] = pack2(wv.y, wv.y);
            sW2[4 * i + 2] = pack2(wv.z, wv.z);
            sW2[4 * i + 3] = pack2(wv.w, wv.w);
        }
    }
    for (int i = tid; i < N_MID * HIDDEN; i += BLOCK)
        sB2[i] = pack2(b_mid[i], 0.0f);
    if (tid < HIDDEN) {
        const float wv = W_out[tid];
        sWout2[tid] = pack2(wv, wv);
        sbin[tid]   = b_in[tid];
    }
    if (tid < HIDDEN * 2) sWin[tid] = W_in[tid];
    if (tid == 0) sbout = b_out[0];
    __syncthreads();

    if (gid >= n) return;

    const float t  = xi.x;
    const float xs = xi.y;

    // Packed forward-mode state: hu=(h,dh/dt), vw=(dh/dx,d2h/dx2); ping-pong.
    ull huA[HIDDEN], vwA[HIDDEN], huB[HIDDEN], vwB[HIDDEN];

    // ---- input layer ----
    #pragma unroll
    for (int j = 0; j < HIDDEN; j++) {
        const float w0 = sWin[2 * j];
        const float w1 = sWin[2 * j + 1];
        const float z  = fmaf(w0, t, fmaf(w1, xs, sbin[j]));
        const float a  = tanh_fast(z);
        const float d  = fmaf(-a, a, 1.0f);
        const float nv = d * w1;
        huA[j] = pack2(a, d * w0);
        vwA[j] = pack2(nv, (-2.0f) * (a * nv) * w1);
    }

    // ---- mid layers, ping-pong (no state copies) ----
    #pragma unroll 1
    for (int lp = 0; lp < N_MID; lp += 2) {
        mid_layer(&sW2[(lp    ) * HIDDEN * HIDDEN], &sB2[(lp    ) * HIDDEN],
                  huA, vwA, huB, vwB);
        mid_layer(&sW2[(lp + 1) * HIDDEN * HIDDEN], &sB2[(lp + 1) * HIDDEN],
                  huB, vwB, huA, vwA);
    }

    // ---- output layer (linear) ----
    ull fhu = pack2(sbout, 0.0f);
    ull fvw = 0ull;
    #pragma unroll
    for (int k2 = 0; k2 < HIDDEN / 2; k2++) {
        const ulonglong2 ww = reinterpret_cast<const ulonglong2*>(sWout2)[k2];
        const int k = 2 * k2;
        fhu = fma2(ww.x, huA[k],     fhu);
        fvw = fma2(ww.x, vwA[k],     fvw);
        fhu = fma2(ww.y, huA[k + 1], fhu);
        fvw = fma2(ww.y, vwA[k + 1], fvw);
    }
    float f, fu, fv, fw;
    unpack2(fhu, f, fu);
    unpack2(fvw, fv, fw);

    const float pde = CBF * xs * xs
                    + fu
                    + 0.5f * CSIGMA * CSIGMA * fw
                    + CB * xs * fv
                    - (CC * CC / (4.0f * CCF)) * fv * fv;

    out[gid]     = f;
    out[n + gid] = pde;
}

extern "C" void kernel_launch(void* const* d_in, const int* in_sizes, int n_in,
                              void* d_out, int out_size)
{
    const float* x     = (const float*)d_in[0];
    const float* W_in  = (const float*)d_in[1];
    const float* b_in  = (const float*)d_in[2];
    const float* W_mid = (const float*)d_in[3];
    const float* b_mid = (const float*)d_in[4];
    const float* W_out = (const float*)d_in[5];
    const float* b_out = (const float*)d_in[6];
    float* out = (float*)d_out;

    const int n = in_sizes[0] / 2;   // x is (N, 2)
    const int blocks = (n + BLOCK - 1) / BLOCK;
    pde_mlp_kernel<<<blocks, BLOCK>>>(x, W_in, b_in, W_mid, b_mid,
                                      W_out, b_out, out, n);
}

// round 16
// speedup vs baseline: 1.0211x; 1.0211x over previous
#include <cuda_runtime.h>

#define HIDDEN  20
#define N_MID   8

#define CB     0.5f
#define CC     0.5f
#define CSIGMA 1.0f
#define CBF    0.5f
#define CCF    0.9f

typedef unsigned long long ull;

// ---------------- packed f32x2 helpers (Blackwell) ----------------
__device__ __forceinline__ ull pack2(float lo, float hi) {
    ull r;
    asm("mov.b64 %0, {%1, %2};" : "=l"(r) : "f"(lo), "f"(hi));
    return r;
}
__device__ __forceinline__ void unpack2(ull p, float& lo, float& hi) {
    asm("mov.b64 {%0, %1}, %2;" : "=f"(lo), "=f"(hi) : "l"(p));
}
__device__ __forceinline__ ull fma2(ull a, ull b, ull c) {
    ull r;
    asm("fma.rn.f32x2 %0, %1, %2, %3;" : "=l"(r) : "l"(a), "l"(b), "l"(c));
    return r;
}

// Hardware tanh: single MUFU.TANH (abs err ~2^-11; final rel_err ~2e-5, safe).
__device__ __forceinline__ float tanh_fast(float z) {
    float r;
    asm("tanh.approx.f32 %0, %1;" : "=f"(r) : "f"(z));
    return r;
}

// One mid layer: (hu,vw) -> (nhu,nvw). Single accumulator pair per stream
// (bank-bound regime: 2 chains x rt3 = 6 cyc/step > lat 5 -> no ILP loss).
__device__ __forceinline__ void mid_layer(const ull* __restrict__ Wl,
                                          const ull* __restrict__ bl,
                                          const ull hu[HIDDEN],
                                          const ull vw[HIDDEN],
                                          ull nhu[HIDDEN],
                                          ull nvw[HIDDEN])
{
    #pragma unroll
    for (int j = 0; j < HIDDEN; j++) {
        ull zhu = bl[j];                  // (b, 0)
        ull zvw = 0ull;
        const ulonglong2* __restrict__ Wrow =
            reinterpret_cast<const ulonglong2*>(&Wl[j * HIDDEN]);
        #pragma unroll
        for (int k2 = 0; k2 < HIDDEN / 2; k2++) {
            const ulonglong2 ww = Wrow[k2];          // LDS.128: (w_k,w_k),(w_k1,w_k1)
            const int k = 2 * k2;
            zhu = fma2(ww.x, hu[k],     zhu);
            zvw = fma2(ww.x, vw[k],     zvw);
            zhu = fma2(ww.y, hu[k + 1], zhu);
            zvw = fma2(ww.y, vw[k + 1], zvw);
        }
        float z, zu, zv, zw;
        unpack2(zhu, z, zu);
        unpack2(zvw, zv, zw);
        const float a  = tanh_fast(z);
        const float d  = fmaf(-a, a, 1.0f);
        const float nv = d * zv;
        const float t  = (-2.0f) * (a * nv);   // FMUL-imm (rt=1) + FMUL
        nhu[j] = pack2(a, d * zu);
        nvw[j] = pack2(nv, fmaf(t, zv, d * zw));
    }
}

__global__ __launch_bounds__(128, 1)
void pde_mlp_kernel(const float* __restrict__ x,
                    const float* __restrict__ W_in,
                    const float* __restrict__ b_in,
                    const float* __restrict__ W_mid,
                    const float* __restrict__ b_mid,
                    const float* __restrict__ W_out,
                    const float* __restrict__ b_out,
                    float* __restrict__ out,
                    int n)
{
    __shared__ __align__(16) ull sW2[N_MID * HIDDEN * HIDDEN];   // (w,w) pairs, 25.6 KB
    __shared__ ull sB2[N_MID * HIDDEN];                          // (b,0)
    __shared__ __align__(16) ull sWout2[HIDDEN];
    __shared__ float sWin[HIDDEN * 2];
    __shared__ float sbin[HIDDEN];
    __shared__ float sbout;

    const int tid = threadIdx.x;
    const int gid = blockIdx.x * blockDim.x + tid;

    // Hoisted point load: LDG issues before the fill, latency hidden behind it.
    float2 xi = make_float2(0.0f, 0.0f);
    if (gid < n) xi = reinterpret_cast<const float2*>(x)[gid];

    // ---- weight fill, vectorized: 800 float4 LDG.128 across 128 threads ----
    {
        const float4* __restrict__ Wm4 = reinterpret_cast<const float4*>(W_mid);
        #pragma unroll 1
        for (int i = tid; i < (N_MID * HIDDEN * HIDDEN) / 4; i += 128) {
            const float4 wv = Wm4[i];
            sW2[4 * i + 0] = pack2(wv.x, wv.x);
            sW2[4 * i + 1] = pack2(wv.y, wv.y);
            sW2[4 * i + 2] = pack2(wv.z, wv.z);
            sW2[4 * i + 3] = pack2(wv.w, wv.w);
        }
    }
    for (int i = tid; i < N_MID * HIDDEN; i += 128)
        sB2[i] = pack2(b_mid[i], 0.0f);
    if (tid < HIDDEN) {
        const float wv = W_out[tid];
        sWout2[tid] = pack2(wv, wv);
        sbin[tid]   = b_in[tid];
    }
    if (tid < HIDDEN * 2) sWin[tid] = W_in[tid];
    if (tid == 0) sbout = b_out[0];
    __syncthreads();

    if (gid >= n) return;

    const float t  = xi.x;
    const float xs = xi.y;

    // Packed forward-mode state: hu=(h,dh/dt), vw=(dh/dx,d2h/dx2); ping-pong.
    ull huA[HIDDEN], vwA[HIDDEN], huB[HIDDEN], vwB[HIDDEN];

    // ---- input layer ----
    #pragma unroll
    for (int j = 0; j < HIDDEN; j++) {
        const float w0 = sWin[2 * j];
        const float w1 = sWin[2 * j + 1];
        const float z  = fmaf(w0, t, fmaf(w1, xs, sbin[j]));
        const float a  = tanh_fast(z);
        const float d  = fmaf(-a, a, 1.0f);
        const float nv = d * w1;
        huA[j] = pack2(a, d * w0);
        vwA[j] = pack2(nv, (-2.0f) * (a * nv) * w1);
    }

    // ---- mid layers, ping-pong (no state copies) ----
    #pragma unroll 1
    for (int lp = 0; lp < N_MID; lp += 2) {
        mid_layer(&sW2[(lp    ) * HIDDEN * HIDDEN], &sB2[(lp    ) * HIDDEN],
                  huA, vwA, huB, vwB);
        mid_layer(&sW2[(lp + 1) * HIDDEN * HIDDEN], &sB2[(lp + 1) * HIDDEN],
                  huB, vwB, huA, vwA);
    }

    // ---- output layer (linear) ----
    ull fhu = pack2(sbout, 0.0f);
    ull fvw = 0ull;
    #pragma unroll
    for (int k2 = 0; k2 < HIDDEN / 2; k2++) {
        const ulonglong2 ww = reinterpret_cast<const ulonglong2*>(sWout2)[k2];
        const int k = 2 * k2;
        fhu = fma2(ww.x, huA[k],     fhu);
        fvw = fma2(ww.x, vwA[k],     fvw);
        fhu = fma2(ww.y, huA[k + 1], fhu);
        fvw = fma2(ww.y, vwA[k + 1], fvw);
    }
    float f, fu, fv, fw;
    unpack2(fhu, f, fu);
    unpack2(fvw, fv, fw);

    const float pde = CBF * xs * xs
                    + fu
                    + 0.5f * CSIGMA * CSIGMA * fw
                    + CB * xs * fv
                    - (CC * CC / (4.0f * CCF)) * fv * fv;

    out[gid]     = f;
    out[n + gid] = pde;
}

extern "C" void kernel_launch(void* const* d_in, const int* in_sizes, int n_in,
                              void* d_out, int out_size)
{
    const float* x     = (const float*)d_in[0];
    const float* W_in  = (const float*)d_in[1];
    const float* b_in  = (const float*)d_in[2];
    const float* W_mid = (const float*)d_in[3];
    const float* b_mid = (const float*)d_in[4];
    const float* W_out = (const float*)d_in[5];
    const float* b_out = (const float*)d_in[6];
    float* out = (float*)d_out;

    const int n = in_sizes[0] / 2;   // x is (N, 2)
    const int threads = 128;
    const int blocks  = (n + threads - 1) / threads;
    pde_mlp_kernel<<<blocks, threads>>>(x, W_in, b_in, W_mid, b_mid,
                                        W_out, b_out, out, n);
}

// round 17
// speedup vs baseline: 1.0250x; 1.0037x over previous
#include <cuda_runtime.h>

#define HIDDEN  20
#define N_MID   8

#define CB     0.5f
#define CC     0.5f
#define CSIGMA 1.0f
#define CBF    0.5f
#define CCF    0.9f

typedef unsigned long long ull;

// ---------------- packed f32x2 helpers (Blackwell) ----------------
__device__ __forceinline__ ull pack2(float lo, float hi) {
    ull r;
    asm("mov.b64 %0, {%1, %2};" : "=l"(r) : "f"(lo), "f"(hi));
    return r;
}
__device__ __forceinline__ void unpack2(ull p, float& lo, float& hi) {
    asm("mov.b64 {%0, %1}, %2;" : "=f"(lo), "=f"(hi) : "l"(p));
}
__device__ __forceinline__ ull fma2(ull a, ull b, ull c) {
    ull r;
    asm("fma.rn.f32x2 %0, %1, %2, %3;" : "=l"(r) : "l"(a), "l"(b), "l"(c));
    return r;
}

// Hardware tanh: single MUFU.TANH (abs err ~2^-11; final rel_err ~2e-5, safe).
__device__ __forceinline__ float tanh_fast(float z) {
    float r;
    asm("tanh.approx.f32 %0, %1;" : "=f"(r) : "f"(z));
    return r;
}

// One mid layer: (hu,vw) -> (nhu,nvw). Single accumulator pair per stream
// (bank-bound regime: 2 chains x rt3 = 6 cyc/step > lat 5 -> no ILP loss).
__device__ __forceinline__ void mid_layer(const ull* __restrict__ Wl,
                                          const ull* __restrict__ bl,
                                          const ull hu[HIDDEN],
                                          const ull vw[HIDDEN],
                                          ull nhu[HIDDEN],
                                          ull nvw[HIDDEN])
{
    #pragma unroll
    for (int j = 0; j < HIDDEN; j++) {
        ull zhu = bl[j];                  // (b, 0)
        ull zvw = 0ull;
        const ulonglong2* __restrict__ Wrow =
            reinterpret_cast<const ulonglong2*>(&Wl[j * HIDDEN]);
        #pragma unroll
        for (int k2 = 0; k2 < HIDDEN / 2; k2++) {
            const ulonglong2 ww = Wrow[k2];          // LDS.128: (w_k,w_k),(w_k1,w_k1)
            const int k = 2 * k2;
            zhu = fma2(ww.x, hu[k],     zhu);
            zvw = fma2(ww.x, vw[k],     zvw);
            zhu = fma2(ww.y, hu[k + 1], zhu);
            zvw = fma2(ww.y, vw[k + 1], zvw);
        }
        float z, zu, zv, zw;
        unpack2(zhu, z, zu);
        unpack2(zvw, zv, zw);
        const float a  = tanh_fast(z);
        const float d  = fmaf(-a, a, 1.0f);
        const float nv = d * zv;
        const float t  = (-2.0f) * (a * nv);   // FMUL-imm (rt=1) + FMUL
        nhu[j] = pack2(a, d * zu);
        nvw[j] = pack2(nv, fmaf(t, zv, d * zw));
    }
}

__global__ __launch_bounds__(128, 1)
void pde_mlp_kernel(const float* __restrict__ x,
                    const float* __restrict__ W_in,
                    const float* __restrict__ b_in,
                    const float* __restrict__ W_mid,
                    const float* __restrict__ b_mid,
                    const float* __restrict__ W_out,
                    const float* __restrict__ b_out,
                    float* __restrict__ out,
                    int n)
{
    __shared__ __align__(16) ull sW2[N_MID * HIDDEN * HIDDEN];   // (w,w) pairs, 25.6 KB
    __shared__ ull sB2[N_MID * HIDDEN];                          // (b,0)
    __shared__ __align__(16) ull sWout2[HIDDEN];
    __shared__ float sWin[HIDDEN * 2];
    __shared__ float sbin[HIDDEN];
    __shared__ float sbout;

    const int tid = threadIdx.x;
    const int gid = blockIdx.x * blockDim.x + tid;

    // Hoisted point load: LDG issues before the fill, latency hidden behind it.
    float2 xi = make_float2(0.0f, 0.0f);
    if (gid < n) xi = reinterpret_cast<const float2*>(x)[gid];

    // ---- weight fill, vectorized: 800 float4 LDG.128 across 128 threads ----
    {
        const float4* __restrict__ Wm4 = reinterpret_cast<const float4*>(W_mid);
        #pragma unroll 1
        for (int i = tid; i < (N_MID * HIDDEN * HIDDEN) / 4; i += 128) {
            const float4 wv = Wm4[i];
            sW2[4 * i + 0] = pack2(wv.x, wv.x);
            sW2[4 * i + 1] = pack2(wv.y, wv.y);
            sW2[4 * i + 2] = pack2(wv.z, wv.z);
            sW2[4 * i + 3] = pack2(wv.w, wv.w);
        }
    }
    for (int i = tid; i < N_MID * HIDDEN; i += 128)
        sB2[i] = pack2(b_mid[i], 0.0f);
    if (tid < HIDDEN) {
        const float wv = W_out[tid];
        sWout2[tid] = pack2(wv, wv);
        sbin[tid]   = b_in[tid];
    }
    if (tid < HIDDEN * 2) sWin[tid] = W_in[tid];
    if (tid == 0) sbout = b_out[0];
    __syncthreads();

    if (gid >= n) return;

    const float t  = xi.x;
    const float xs = xi.y;

    // Packed forward-mode state: hu=(h,dh/dt), vw=(dh/dx,d2h/dx2); ping-pong.
    ull huA[HIDDEN], vwA[HIDDEN], huB[HIDDEN], vwB[HIDDEN];

    // ---- input layer ----
    #pragma unroll
    for (int j = 0; j < HIDDEN; j++) {
        const float w0 = sWin[2 * j];
        const float w1 = sWin[2 * j + 1];
        const float z  = fmaf(w0, t, fmaf(w1, xs, sbin[j]));
        const float a  = tanh_fast(z);
        const float d  = fmaf(-a, a, 1.0f);
        const float nv = d * w1;
        huA[j] = pack2(a, d * w0);
        vwA[j] = pack2(nv, (-2.0f) * (a * nv) * w1);
    }

    // ---- mid layers, ping-pong (no state copies) ----
    #pragma unroll 1
    for (int lp = 0; lp < N_MID; lp += 2) {
        mid_layer(&sW2[(lp    ) * HIDDEN * HIDDEN], &sB2[(lp    ) * HIDDEN],
                  huA, vwA, huB, vwB);
        mid_layer(&sW2[(lp + 1) * HIDDEN * HIDDEN], &sB2[(lp + 1) * HIDDEN],
                  huB, vwB, huA, vwA);
    }

    // ---- output layer (linear) ----
    ull fhu = pack2(sbout, 0.0f);
    ull fvw = 0ull;
    #pragma unroll
    for (int k2 = 0; k2 < HIDDEN / 2; k2++) {
        const ulonglong2 ww = reinterpret_cast<const ulonglong2*>(sWout2)[k2];
        const int k = 2 * k2;
        fhu = fma2(ww.x, huA[k],     fhu);
        fvw = fma2(ww.x, vwA[k],     fvw);
        fhu = fma2(ww.y, huA[k + 1], fhu);
        fvw = fma2(ww.y, vwA[k + 1], fvw);
    }
    float f, fu, fv, fw;
    unpack2(fhu, f, fu);
    unpack2(fvw, fv, fw);

    const float pde = CBF * xs * xs
                    + fu
                    + 0.5f * CSIGMA * CSIGMA * fw
                    + CB * xs * fv
                    - (CC * CC / (4.0f * CCF)) * fv * fv;

    out[gid]     = f;
    out[n + gid] = pde;
}

extern "C" void kernel_launch(void* const* d_in, const int* in_sizes, int n_in,
                              void* d_out, int out_size)
{
    const float* x     = (const float*)d_in[0];
    const float* W_in  = (const float*)d_in[1];
    const float* b_in  = (const float*)d_in[2];
    const float* W_mid = (const float*)d_in[3];
    const float* b_mid = (const float*)d_in[4];
    const float* W_out = (const float*)d_in[5];
    const float* b_out = (const float*)d_in[6];
    float* out = (float*)d_out;

    const int n = in_sizes[0] / 2;   // x is (N, 2)
    const int threads = 128;
    const int blocks  = (n + threads - 1) / threads;
    pde_mlp_kernel<<<blocks, threads>>>(x, W_in, b_in, W_mid, b_mid,
                                        W_out, b_out, out, n);
}